// round 16
// baseline (speedup 1.0000x reference)
#include <cuda_runtime.h>
#include <cuda_bf16.h>

// Cascaded 16-tap FIR pair == single 33-tap causal conv for columns i >= 32:
//   y[i] = x[i] + sum_{j=1}^{32} g[j] * x[i-j],  g = [1,h] (*) [1,h_rev]
// Columns [0,32) computed exactly (v-mask aware) by lanes 0-1 on row-start tiles.
//
// ROW-PAIRED fma.rn.f32x2, RPT=16 cols/lane (512-col warp-tiles): window
// amplification drops 5x -> 3x (24 LDS.128 / 1024 outputs). Interleaved tile
// stored as even/odd parity planes of 8-pair segments (20-float padded stride)
// so the stride-2 segment access stays bank-conflict-free. Taps broadcast from
// smem (1 wavefront per LDS.128). Two 8-output halves computed high-first so
// wd[0..7] loads late and wd[40..47] dies early (reg peak ~120).
// Barrier-free contiguous warp streams, double-buffered cp.async.
//
// B=256 rows, N=131072 cols, F=16.

#define F       16
#define GT      33
#define THREADS 256
#define WARPS   8
#define WCOLS   512                // output columns per warp-tile (x 2 rows)
#define HALO    32
#define SPAN    (WCOLS + HALO)     // 544 staged columns
#define NCOL    131072
#define NROW    256
#define TPR     (NCOL / WCOLS)     // 256 tiles per row-pair
#define NWT     (TPR * (NROW / 2)) // 32768 warp-tiles
#define NBLK    296                // 2 CTAs per SM
#define NSTREAM (NBLK * WARPS)     // 2368 warp streams
#define QT      (NWT / NSTREAM)    // 13
#define RT      (NWT % NSTREAM)    // 1984 streams get one extra

// Interleaved tile as two parity planes: 34 segments x 8 col-pairs each,
// padded 16 -> 20 floats per segment. Even plane @0, odd plane @EV.
#define EV      680                        // 34 * 20 floats
#define BUFW    (2 * EV)                   // 1360 floats per buffer
#define TAP_OFF (2 * BUFW)                 // 2720: 32 float2 tap pairs
#define WSLOT   (TAP_OFF + 64)             // 2784 floats per warp
#define SMEM_DYN (WARPS * WSLOT * 4)       // 89088 B

typedef unsigned long long u64;

#define FMA2(d, a, b, c) \
    asm("fma.rn.f32x2 %0, %1, %2, %3;" : "=l"(d) : "l"(a), "l"(b), "l"(c))
#define UNPACK2(lo, hi, p) \
    asm("mov.b64 {%0, %1}, %2;" : "=f"(lo), "=f"(hi) : "l"(p))

__device__ __forceinline__ void cp4(unsigned dst, const float* src, int sz) {
    asm volatile("cp.async.ca.shared.global [%0], [%1], 4, %2;"
                 :: "r"(dst), "l"(src), "r"(sz));
}
__device__ __forceinline__ void cp_commit() {
    asm volatile("cp.async.commit_group;");
}
template <int N> __device__ __forceinline__ void cp_wait() {
    asm volatile("cp.async.wait_group %0;" :: "n"(N));
}

// Stage warp-tile wt: staged col sc in [0,544) holds (x0[.], x1[.]) at
// plane(par) + 20*(sc>>4) + 2*(sc&7) + row.
__device__ __forceinline__ void stage_wt(unsigned sb, const float* x,
                                         int wt, int lane)
{
    const int p   = wt / TPR;
    const int tir = wt % TPR;
    const float* s0 = x + ((size_t)p * 2) * NCOL + tir * WCOLS - HALO;
    const float* s1 = s0 + NCOL;
    if (tir != 0) {
#pragma unroll
        for (int k = 0; k < SPAN / 32; k++) {      // 17 iters
            const int sc = lane + 32 * k;
            const unsigned d = sb +
                ((((sc >> 3) & 1) * EV + 20 * (sc >> 4) + 2 * (sc & 7)) << 2);
            cp4(d, s0 + sc, 4);
            cp4(d + 4, s1 + sc, 4);
        }
    } else {
#pragma unroll
        for (int k = 0; k < SPAN / 32; k++) {
            const int sc = lane + 32 * k;
            const int sz = (sc < HALO) ? 0 : 4;
            const float* a = sz ? (s0 + sc) : x;
            const float* b = sz ? (s1 + sc) : x;
            const unsigned d = sb +
                ((((sc >> 3) & 1) * EV + 20 * (sc >> 4) + 2 * (sc & 7)) << 2);
            cp4(d, a, sz);
            cp4(d + 4, b, sz);
        }
    }
}

// Load 8 pairs (one padded segment) into wd[i..i+8).
__device__ __forceinline__ void ld_seg(u64* wd, const float* p) {
#pragma unroll
    for (int q = 0; q < 4; q++) {
        const ulonglong2 v = *reinterpret_cast<const ulonglong2*>(p + 4 * q);
        wd[2 * q]     = v.x;
        wd[2 * q + 1] = v.y;
    }
}

__global__ __launch_bounds__(THREADS, 2)
void fir2_fused(const float* __restrict__ x,
                const float* __restrict__ h,
                float* __restrict__ y)
{
    extern __shared__ float smem[];

    const int tid  = threadIdx.x;
    const int wid  = tid >> 5;
    const int lane = tid & 31;

    float* const wbase = smem + wid * WSLOT;
    float* const tapf  = wbase + TAP_OFF;
    const unsigned sbw = (unsigned)__cvta_generic_to_shared(wbase);

    // ---- combined taps: lane computes g[lane+1], writes (g,g) to smem ------
    float hh[F];
#pragma unroll
    for (int j = 0; j < F; j++) hh[j] = __ldg(h + j);
    {
        const int j = lane + 1;                // 1..32
        float acc = 0.0f;
        const int a0 = (j > F) ? (j - F) : 0;
        const int a1 = (j < F) ? j : F;
#pragma unroll
        for (int a = 0; a <= F; a++) {
            if (a >= a0 && a <= a1) {
                const float ka = (a == 0) ? 1.0f : hh[a - 1];
                const int bb = j - a;
                const float kb = (bb == 0) ? 1.0f : hh[F - bb];
                acc += ka * kb;
            }
        }
        *reinterpret_cast<float2*>(tapf + 2 * lane) = make_float2(acc, acc);
    }
    __syncwarp();

    // ---- contiguous stream range -------------------------------------------
    const int S     = blockIdx.x * WARPS + wid;
    const int start = S * QT + ((S < RT) ? S : RT);
    const int cnt   = QT + (S < RT ? 1 : 0);

    stage_wt(sbw, x, start, lane);
    cp_commit();

    int buf = 0;
    for (int i = 0; i < cnt; i++, buf ^= 1) {
        cp_wait<0>();                      // tile i landed
        __syncwarp();                      // all lanes done reading buf^1
        if (i + 1 < cnt)
            stage_wt(sbw + (buf ^ 1) * (BUFW * 4), x, start + i + 1, lane);
        cp_commit();

        const int wt  = start + i;
        const int p   = wt / TPR;
        const int tir = wt % TPR;
        const int t0  = tir * WCOLS;
        const size_t r0off = (size_t)p * 2 * NCOL;
        const float* sxc = wbase + buf * BUFW;

        if (!(tir == 0 && lane < 2)) {
            // wd[q] = pair at staged col 16*lane + q, q in [0,48):
            // group k: even seg (lane+k) -> wd[16k..16k+8),
            //          odd  seg (lane+k) -> wd[16k+8..16k+16)
            u64 wd[48];
            ld_seg(wd + 8,  sxc + EV + 20 * lane);           // odd k=0
            ld_seg(wd + 16, sxc +      20 * (lane + 1));
            ld_seg(wd + 24, sxc + EV + 20 * (lane + 1));
            ld_seg(wd + 32, sxc +      20 * (lane + 2));
            ld_seg(wd + 40, sxc + EV + 20 * (lane + 2));

            float o0[16], o1[16];

            // ---- high half first (o in [8,16)): uses wd[8..47] -------------
#pragma unroll
            for (int half = 1; half >= 0; half--) {
                const int ho = 8 * half;
                if (half == 0)
                    ld_seg(wd, sxc + 20 * lane);             // even k=0, late
                u64 acc[8];
#pragma unroll
                for (int r = 0; r < 8; r++) acc[r] = wd[32 + ho + r];
#pragma unroll
                for (int c = 0; c < 4; c++) {
                    u64 tq[8];
                    ld_seg(tq, tapf + 16 * c);               // broadcast
#pragma unroll
                    for (int k = 1; k <= 8; k++) {
#pragma unroll
                        for (int r = 0; r < 8; r++)
                            FMA2(acc[r], tq[k - 1],
                                 wd[32 + ho + r - 8 * c - k], acc[r]);
                    }
                }
#pragma unroll
                for (int r = 0; r < 8; r++)
                    UNPACK2(o0[ho + r], o1[ho + r], acc[r]);
            }

            float4* y0 = reinterpret_cast<float4*>(y + r0off + t0 + 16 * lane);
            float4* y1 = reinterpret_cast<float4*>(y + r0off + NCOL + t0 + 16 * lane);
#pragma unroll
            for (int q = 0; q < 4; q++) {
                y0[q] = make_float4(o0[4 * q], o0[4 * q + 1],
                                    o0[4 * q + 2], o0[4 * q + 3]);
                y1[q] = make_float4(o1[4 * q], o1[4 * q + 1],
                                    o1[4 * q + 2], o1[4 * q + 3]);
            }
        } else if (lane == 0) {
            // cols [0,16) = 0 for both rows
#pragma unroll
            for (int rr = 0; rr < 2; rr++) {
                float4* yo = reinterpret_cast<float4*>(y + r0off + rr * NCOL);
#pragma unroll
                for (int q = 0; q < 4; q++)
                    yo[q] = make_float4(0.f, 0.f, 0.f, 0.f);
            }
        } else {
            // lane 1: exact masked two-stage result, cols [16,32), both rows
#pragma unroll
            for (int rr = 0; rr < 2; rr++) {
                const float* xr = x + r0off + rr * NCOL;
                float xa[32];
#pragma unroll
                for (int cc = 0; cc < 32; cc++) xa[cc] = xr[cc];

                float va[F];               // v[16..31]
#pragma unroll
                for (int tt = 0; tt < F; tt++) {
                    const int k = F + tt;
                    float a2 = xa[k];
#pragma unroll
                    for (int j = 0; j < F; j++)
                        a2 = fmaf(hh[j], xa[k - 1 - j], a2);
                    va[tt] = a2;
                }
                float ya[F];               // y[16..31]
#pragma unroll
                for (int tt = 0; tt < F; tt++) {
                    const int i2 = F + tt;
                    float a2 = va[tt];
#pragma unroll
                    for (int m = 0; m < F; m++) {
                        const int k = i2 - F + m;  // v index; masked if < 16
                        if (k >= F) a2 = fmaf(hh[m], va[k - F], a2);
                    }
                    ya[tt] = a2;
                }
                float4* yo = reinterpret_cast<float4*>(y + r0off + rr * NCOL + F);
#pragma unroll
                for (int q = 0; q < 4; q++)
                    yo[q] = make_float4(ya[4 * q], ya[4 * q + 1],
                                        ya[4 * q + 2], ya[4 * q + 3]);
            }
        }
    }
}

extern "C" void kernel_launch(void* const* d_in, const int* in_sizes, int n_in,
                              void* d_out, int out_size)
{
    const float* x = (const float*)d_in[0];   // (256, 131072) f32
    const float* h = (const float*)d_in[1];   // (1, 16) f32
    float* y = (float*)d_out;                 // (256, 131072) f32

    cudaFuncSetAttribute(fir2_fused,
                         cudaFuncAttributeMaxDynamicSharedMemorySize, SMEM_DYN);
    fir2_fused<<<NBLK, THREADS, SMEM_DYN>>>(x, h, y);
}